// round 4
// baseline (speedup 1.0000x reference)
#include <cuda_runtime.h>
#include <math.h>
#include <stdint.h>

// ---------------- problem constants ----------------
#define BB 2
#define TT 4096
#define BT (BB*TT)          // 8192
#define DM 2048
#define NH 16
#define DK_ 128
#define DV_ 128
#define CH 64               // chunk
#define NC (TT/CH)          // 64 chunks
#define NVS 4               // dv splits in scan
#define WV (DV_/NVS)        // 32

// ---------------- scratch (device globals; no allocs) ----------------
__device__ float d_qpre[(size_t)BT*DM];
__device__ float d_kpre[(size_t)BT*DM];
__device__ float d_vpre[(size_t)BT*DM];
__device__ float d_q[(size_t)BT*DM];
__device__ float d_k[(size_t)BT*DM];
__device__ float d_v[(size_t)BT*DM];
__device__ float d_g[(size_t)BT*DM];
__device__ float d_gate[(size_t)BT*DM];
__device__ float d_wcat[(size_t)DM*256];
__device__ float d_glowcat[(size_t)BT*256];
__device__ float d_beta[(size_t)BT*NH];
__device__ float d_qt[(size_t)BT*DM];
__device__ float d_kt[(size_t)BT*DM];
__device__ float d_kd[(size_t)BT*DM];
__device__ float d_attn[(size_t)BB*NH*NC*CH*CH];
__device__ float d_tinv[(size_t)BB*NH*NC*CH*CH];
__device__ float d_dec[(size_t)BB*NH*NC*DK_];
__device__ float d_o[(size_t)BT*DM];
__device__ float d_og[(size_t)BT*DM];

// ---------------- tf32 helpers ----------------
__device__ __forceinline__ uint32_t f2tf32(float x)
{
    uint32_t y;
    asm("cvt.rna.tf32.f32 %0, %1;" : "=r"(y) : "f"(x));
    return y;
}

__device__ __forceinline__ void mma_tf32(float* c, const uint32_t* a, const uint32_t* b)
{
    asm volatile(
        "mma.sync.aligned.m16n8k8.row.col.f32.tf32.tf32.f32 "
        "{%0,%1,%2,%3}, {%4,%5,%6,%7}, {%8,%9}, {%0,%1,%2,%3};"
        : "+f"(c[0]), "+f"(c[1]), "+f"(c[2]), "+f"(c[3])
        : "r"(a[0]), "r"(a[1]), "r"(a[2]), "r"(a[3]), "r"(b[0]), "r"(b[1]));
}

// ---------------- tf32 tensor-core GEMM v2 ----------------
// C[M,N] = A[M,K] @ B[K,N], leading dims lda/ldb/ldc.
// BM x BN block tile, 64x64 warp tile (MT=4 m16, NT=8 n8), BK=16.
// Double-buffered smem, single sync per K-tile, register-staged global loads.
// Requires M%BM==0, N%BN==0, K%16==0.
template<int BM, int BN>
__global__ void __launch_bounds__((BM/64)*(BN/64)*32)
gemm2(const float* __restrict__ A, int lda,
      const float* __restrict__ B, int ldb,
      float* __restrict__ C, int ldc,
      int M, int N, int K)
{
    constexpr int WARPS = (BM/64)*(BN/64);
    constexpr int THR   = WARPS * 32;
    constexpr int ASD   = BM + 8;
    constexpr int BSD   = BN + 8;
    constexpr int ASZ   = 16 * ASD;
    constexpr int BSZ   = 16 * BSD;
    constexpr int ALD4  = (BM * 16) / (4 * THR);
    constexpr int BLD4  = (BN * 16) / (4 * THR);
    constexpr int NW    = BN / 64;          // warps along N

    extern __shared__ uint32_t sm2[];
    uint32_t* AsB[2] = { sm2,             sm2 + (ASZ + BSZ) };
    uint32_t* BsB[2] = { sm2 + ASZ,       sm2 + (ASZ + BSZ) + ASZ };

    const int bm = blockIdx.y * BM;
    const int bn = blockIdx.x * BN;
    const int tid  = threadIdx.x;
    const int lane = tid & 31;
    const int wid  = tid >> 5;
    const int wm = (wid / NW) * 64;
    const int wn = (wid % NW) * 64;

    float4 ra[ALD4], rb[BLD4];

    float acc[4][8][4];
#pragma unroll
    for (int mt = 0; mt < 4; mt++)
#pragma unroll
        for (int nt = 0; nt < 8; nt++)
#pragma unroll
            for (int e = 0; e < 4; e++) acc[mt][nt][e] = 0.f;

    auto ldG = [&](int k0) {
#pragma unroll
        for (int i = 0; i < ALD4; i++) {
            int lin = tid + i * THR;
            int m = lin >> 2, kq = (lin & 3) * 4;
            ra[i] = *reinterpret_cast<const float4*>(&A[(size_t)(bm + m) * lda + k0 + kq]);
        }
#pragma unroll
        for (int i = 0; i < BLD4; i++) {
            int lin = tid + i * THR;
            int kk = lin / (BN / 4), nq = (lin % (BN / 4)) * 4;
            rb[i] = *reinterpret_cast<const float4*>(&B[(size_t)(k0 + kk) * ldb + bn + nq]);
        }
    };
    auto stS = [&](int p) {
        uint32_t* As = AsB[p];
        uint32_t* Bs = BsB[p];
#pragma unroll
        for (int i = 0; i < ALD4; i++) {
            int lin = tid + i * THR;
            int m = lin >> 2, kq = (lin & 3) * 4;
            As[(kq + 0) * ASD + m] = f2tf32(ra[i].x);
            As[(kq + 1) * ASD + m] = f2tf32(ra[i].y);
            As[(kq + 2) * ASD + m] = f2tf32(ra[i].z);
            As[(kq + 3) * ASD + m] = f2tf32(ra[i].w);
        }
#pragma unroll
        for (int i = 0; i < BLD4; i++) {
            int lin = tid + i * THR;
            int kk = lin / (BN / 4), nq = (lin % (BN / 4)) * 4;
            Bs[kk * BSD + nq + 0] = f2tf32(rb[i].x);
            Bs[kk * BSD + nq + 1] = f2tf32(rb[i].y);
            Bs[kk * BSD + nq + 2] = f2tf32(rb[i].z);
            Bs[kk * BSD + nq + 3] = f2tf32(rb[i].w);
        }
    };

    ldG(0);
    stS(0);
    __syncthreads();

    int p = 0;
    for (int k0 = 0; k0 < K; k0 += 16) {
        const bool nxt = (k0 + 16) < K;
        if (nxt) ldG(k0 + 16);
        const uint32_t* As = AsB[p];
        const uint32_t* Bs = BsB[p];
#pragma unroll
        for (int ks = 0; ks < 16; ks += 8) {
            const int kc = ks + (lane & 3);
            uint32_t af[4][4];
#pragma unroll
            for (int mt = 0; mt < 4; mt++) {
                int r = wm + mt * 16 + (lane >> 2);
                af[mt][0] = As[kc * ASD + r];
                af[mt][1] = As[kc * ASD + r + 8];
                af[mt][2] = As[(kc + 4) * ASD + r];
                af[mt][3] = As[(kc + 4) * ASD + r + 8];
            }
            uint32_t bf[8][2];
#pragma unroll
            for (int nt = 0; nt < 8; nt++) {
                int cN = wn + nt * 8 + (lane >> 2);
                bf[nt][0] = Bs[kc * BSD + cN];
                bf[nt][1] = Bs[(kc + 4) * BSD + cN];
            }
#pragma unroll
            for (int mt = 0; mt < 4; mt++)
#pragma unroll
                for (int nt = 0; nt < 8; nt++)
                    mma_tf32(acc[mt][nt], af[mt], bf[nt]);
        }
        if (nxt) stS(p ^ 1);
        __syncthreads();
        p ^= 1;
    }

#pragma unroll
    for (int mt = 0; mt < 4; mt++) {
        int r0 = bm + wm + mt * 16 + (lane >> 2);
#pragma unroll
        for (int nt = 0; nt < 8; nt++) {
            int c0 = bn + wn + nt * 8 + (lane & 3) * 2;
            *reinterpret_cast<float2*>(&C[(size_t)r0 * ldc + c0]) =
                make_float2(acc[mt][nt][0], acc[mt][nt][1]);
            *reinterpret_cast<float2*>(&C[(size_t)(r0 + 8) * ldc + c0]) =
                make_float2(acc[mt][nt][2], acc[mt][nt][3]);
        }
    }
}

#define SMEM_G_BIG  ((16*(128+8) + 16*(256+8)) * 2 * 4)
#define SMEM_G_SML  ((16*(128+8) + 16*(128+8)) * 2 * 4)

// ---------------- concat Wad|Wgd -> Wcat[2048,256] ----------------
__global__ void cat_kernel(const float* __restrict__ Wad, const float* __restrict__ Wgd,
                           float* __restrict__ Wcat)
{
    int i = blockIdx.x * blockDim.x + threadIdx.x;   // 0 .. 2048*256-1
    int k = i >> 8, j = i & 255;
    Wcat[i] = (j < 128) ? Wad[k * 128 + j] : Wgd[k * 128 + j - 128];
}

// ---------------- fused beta = sigmoid(clip(x @ Wb)) ----------------
__global__ void beta_kernel(const float* __restrict__ x, const float* __restrict__ Wb,
                            float* __restrict__ beta)
{
    __shared__ float wbs[256][17];
    const int tid  = threadIdx.x;
    const int lane = tid & 31;
    const int wid  = tid >> 5;
    const int row  = blockIdx.x * 8 + wid;

    float acc[16];
#pragma unroll
    for (int c = 0; c < 16; c++) acc[c] = 0.f;

    for (int k0 = 0; k0 < DM; k0 += 256) {
        __syncthreads();
        {
            const float* src = &Wb[(size_t)(k0 + tid) * 16];
#pragma unroll
            for (int c = 0; c < 16; c++) wbs[tid][c] = src[c];
        }
        __syncthreads();
#pragma unroll
        for (int k8 = 0; k8 < 8; k8++) {
            float xv = x[(size_t)row * DM + k0 + k8 * 32 + lane];
#pragma unroll
            for (int c = 0; c < 16; c++) acc[c] += xv * wbs[k8 * 32 + lane][c];
        }
    }
#pragma unroll
    for (int c = 0; c < 16; c++) {
#pragma unroll
        for (int off = 16; off; off >>= 1)
            acc[c] += __shfl_xor_sync(0xffffffffu, acc[c], off);
    }
    if (lane == 0) {
#pragma unroll
        for (int c = 0; c < 16; c++) {
            float v = fminf(fmaxf(acc[c], -10.f), 10.f);
            beta[(size_t)row * 16 + c] = 1.f / (1.f + expf(-v));
        }
    }
}

// ---------------- causal depthwise conv (K=4) + silu (+ per-head l2norm) ----------------
__global__ void conv_silu_kernel(const float* __restrict__ pre, const float* __restrict__ w,
                                 float* __restrict__ out, int do_norm)
{
    __shared__ float ws[4];
    const int blk = blockIdx.x;               // (b*T + t)*NH + h
    const int h  = blk % NH;
    const int bt = blk / NH;
    const int t  = bt % TT;
    const int d  = threadIdx.x;               // 0..127
    const int c  = h * DK_ + d;

    float acc = 0.f;
#pragma unroll
    for (int j = 0; j < 4; j++) {
        int tt = t - 3 + j;
        if (tt >= 0) acc += w[c * 4 + j] * pre[(size_t)(bt - 3 + j) * DM + c];
    }
    float s = acc / (1.f + expf(-acc));       // silu
    if (do_norm) {
        float v = s * s;
#pragma unroll
        for (int o = 16; o > 0; o >>= 1) v += __shfl_down_sync(0xffffffffu, v, o);
        int lane = threadIdx.x & 31, wrp = threadIdx.x >> 5;
        if (lane == 0) ws[wrp] = v;
        __syncthreads();
        if (threadIdx.x == 0) ws[0] = ws[0] + ws[1] + ws[2] + ws[3];
        __syncthreads();
        float n = sqrtf(ws[0]);
        s = s / fmaxf(n, 1e-6f);
    }
    out[(size_t)bt * DM + c] = s;
}

// ---------------- elementwise ----------------
__global__ void gact_kernel(float* __restrict__ p, size_t n)
{
    size_t i = (size_t)blockIdx.x * blockDim.x + threadIdx.x;
    if (i < n) {
        float x = p[i];
        x = fminf(fmaxf(x, -10.f), 10.f);
        p[i] = -log1pf(expf(x));
    }
}
__global__ void sigmoid_kernel(float* __restrict__ p, size_t n)
{
    size_t i = (size_t)blockIdx.x * blockDim.x + threadIdx.x;
    if (i < n) p[i] = 1.f / (1.f + expf(-p[i]));
}

// ---------------- per-chunk prep ----------------
#define PREP_SMEM ((4*64*129 + 2*64*65 + 128 + 64) * 4)
__global__ void prep_kernel()
{
    extern __shared__ float sm[];
    float* s_cum = sm;                    // 64*129
    float* s_kt  = s_cum + 64 * 129;
    float* s_kb  = s_kt  + 64 * 129;
    float* s_qt  = s_kb  + 64 * 129;
    float* s_M   = s_qt  + 64 * 129;      // 64*65
    float* s_X   = s_M   + 64 * 65;       // 64*65
    float* s_bl  = s_X   + 64 * 65;       // 128
    float* s_be  = s_bl  + 128;           // 64

    const int blk = blockIdx.x;           // bh*NC + c
    const int c   = blk % NC;
    const int bh  = blk / NC;
    const int h   = bh % NH;
    const int b   = bh / NH;
    const int t0  = c * CH;
    const int tid = threadIdx.x;
    const size_t rowbase = (size_t)(b * TT + t0) * DM + h * DK_;

    if (tid < 128) {
        float run = 0.f;
        for (int t = 0; t < CH; t++) {
            run += d_g[rowbase + (size_t)t * DM + tid];
            s_cum[t * 129 + tid] = run;
        }
        s_bl[tid] = run;
    }
    if (tid < 64) s_be[tid] = d_beta[(size_t)(b * TT + t0 + tid) * NH + h];
    __syncthreads();

    for (int idx = tid; idx < CH * 128; idx += 256) {
        int t = idx >> 7, d = idx & 127;
        float cum = s_cum[t * 129 + d];
        size_t gi = rowbase + (size_t)t * DM + d;
        float kv = d_k[gi];
        float qv = d_q[gi];
        float e  = expf(cum);
        float kt = kv * e;
        float qt = qv * e;
        float kb = kv * expf(-cum);
        float kd = kv * expf(s_bl[d] - cum);
        s_kt[t * 129 + d] = kt;
        s_qt[t * 129 + d] = qt;
        s_kb[t * 129 + d] = kb;
        d_kt[gi] = kt;
        d_qt[gi] = qt;
        d_kd[gi] = kd;
    }
    if (tid < 128) d_dec[(size_t)blk * 128 + tid] = expf(s_bl[tid]);
    __syncthreads();

    const size_t ab = (size_t)blk * (CH * CH);
    {
        const int tI = (tid >> 4) * 4;
        const int sI = (tid & 15) * 4;
        float a[4][4], at[4][4];
#pragma unroll
        for (int i = 0; i < 4; i++)
#pragma unroll
            for (int j = 0; j < 4; j++) { a[i][j] = 0.f; at[i][j] = 0.f; }
        for (int d = 0; d < 128; d++) {
            float kbv[4], ktv[4], qtv[4];
#pragma unroll
            for (int j = 0; j < 4; j++) kbv[j] = s_kb[(sI + j) * 129 + d];
#pragma unroll
            for (int i = 0; i < 4; i++) { ktv[i] = s_kt[(tI + i) * 129 + d]; qtv[i] = s_qt[(tI + i) * 129 + d]; }
#pragma unroll
            for (int i = 0; i < 4; i++)
#pragma unroll
                for (int j = 0; j < 4; j++) { a[i][j] += ktv[i] * kbv[j]; at[i][j] += qtv[i] * kbv[j]; }
        }
#pragma unroll
        for (int i = 0; i < 4; i++)
#pragma unroll
            for (int j = 0; j < 4; j++) {
                int t = tI + i, s = sI + j;
                s_M[t * 65 + s] = (s < t) ? s_be[t] * a[i][j] : 0.f;
                d_attn[ab + t * 64 + s] = (s <= t) ? at[i][j] : 0.f;
            }
    }
    __syncthreads();

    if (tid < 64) {
        const int j = tid;
        for (int i = 0; i < 64; i++) {
            float x = (i == j) ? 1.f : 0.f;
            for (int l = j; l < i; l++) x -= s_M[i * 65 + l] * s_X[l * 65 + j];
            s_X[i * 65 + j] = x;
        }
        float bj = s_be[j];
        for (int i = 0; i < 64; i++)
            d_tinv[ab + i * 64 + j] = s_X[i * 65 + j] * bj;
    }
}

// ---------------- sequential chunk scan ----------------
#define SCAN_SMEM ((128*33 + 2*64*129 + 2*64*65 + 2*64*33) * 4)
__global__ void scan_kernel()
{
    extern __shared__ float sm[];
    float* sS  = sm;                      // 128*33
    float* sKT = sS  + 128 * 33;          // 64*129 (kt, later kd)
    float* sQT = sKT + 64 * 129;          // 64*129
    float* sAT = sQT + 64 * 129;          // 64*65
    float* sTI = sAT + 64 * 65;           // 64*65
    float* sRH = sTI + 64 * 65;           // 64*33 (v then rhs)
    float* sU  = sRH + 64 * 33;           // 64*33

    const int blk = blockIdx.x;           // bh*NVS + vb
    const int vb  = blk % NVS;
    const int bh  = blk / NVS;
    const int h   = bh % NH;
    const int b   = bh / NH;
    const int dv0 = vb * WV;
    const int tid = threadIdx.x;

    const int tr  = tid >> 4;
    const int tcv = tid & 15;
    const int ur  = tid >> 3;
    const int uc  = tid & 7;

    for (int i = tid; i < 128 * 33; i += 256) sS[i] = 0.f;
    __syncthreads();

    for (int c = 0; c < NC; c++) {
        const int t0 = c * CH;
        const size_t rowbase = (size_t)(b * TT + t0) * DM + h * DK_;
        const size_t ab = (size_t)(bh * NC + c) * (CH * CH);

        for (int i = tid; i < CH * 128; i += 256) {
            int t = i >> 7, d = i & 127;
            size_t gi = rowbase + (size_t)t * DM + d;
            sKT[t * 129 + d] = d_kt[gi];
            sQT[t * 129 + d] = d_qt[gi];
        }
        for (int i = tid; i < CH * CH; i += 256) {
            int t = i >> 6, s = i & 63;
            sAT[t * 65 + s] = d_attn[ab + i];
            sTI[t * 65 + s] = d_tinv[ab + i];
        }
        for (int i = tid; i < CH * WV; i += 256) {
            int t = i >> 5, v = i & 31;
            sRH[t * 33 + v] = d_v[rowbase + (size_t)t * DM + dv0 + v];
        }
        __syncthreads();

        // rhs = v - kt @ S
        {
            float acc[4][2] = {{0.f,0.f},{0.f,0.f},{0.f,0.f},{0.f,0.f}};
            for (int d = 0; d < 128; d++) {
                float kv[4];
#pragma unroll
                for (int i = 0; i < 4; i++) kv[i] = sKT[(tr * 4 + i) * 129 + d];
                float s0 = sS[d * 33 + tcv * 2 + 0];
                float s1 = sS[d * 33 + tcv * 2 + 1];
#pragma unroll
                for (int i = 0; i < 4; i++) { acc[i][0] += kv[i] * s0; acc[i][1] += kv[i] * s1; }
            }
#pragma unroll
            for (int i = 0; i < 4; i++) {
                sRH[(tr * 4 + i) * 33 + tcv * 2 + 0] -= acc[i][0];
                sRH[(tr * 4 + i) * 33 + tcv * 2 + 1] -= acc[i][1];
            }
        }
        __syncthreads();

        for (int i = tid; i < CH * 128; i += 256) {
            int t = i >> 7, d = i & 127;
            sKT[t * 129 + d] = d_kd[rowbase + (size_t)t * DM + d];
        }
        // u = Tinv' @ rhs
        {
            float acc[4][2] = {{0.f,0.f},{0.f,0.f},{0.f,0.f},{0.f,0.f}};
            for (int s = 0; s < 64; s++) {
                float tv[4];
#pragma unroll
                for (int i = 0; i < 4; i++) tv[i] = sTI[(tr * 4 + i) * 65 + s];
                float r0 = sRH[s * 33 + tcv * 2 + 0];
                float r1 = sRH[s * 33 + tcv * 2 + 1];
#pragma unroll
                for (int i = 0; i < 4; i++) { acc[i][0] += tv[i] * r0; acc[i][1] += tv[i] * r1; }
            }
#pragma unroll
            for (int i = 0; i < 4; i++) {
                sU[(tr * 4 + i) * 33 + tcv * 2 + 0] = acc[i][0];
                sU[(tr * 4 + i) * 33 + tcv * 2 + 1] = acc[i][1];
            }
        }
        __syncthreads();

        // o = qt @ S + attn @ u
        {
            float acc[4][2] = {{0.f,0.f},{0.f,0.f},{0.f,0.f},{0.f,0.f}};
            for (int d = 0; d < 128; d++) {
                float qv[4];
#pragma unroll
                for (int i = 0; i < 4; i++) qv[i] = sQT[(tr * 4 + i) * 129 + d];
                float s0 = sS[d * 33 + tcv * 2 + 0];
                float s1 = sS[d * 33 + tcv * 2 + 1];
#pragma unroll
                for (int i = 0; i < 4; i++) { acc[i][0] += qv[i] * s0; acc[i][1] += qv[i] * s1; }
            }
            for (int s = 0; s < 64; s++) {
                float av[4];
#pragma unroll
                for (int i = 0; i < 4; i++) av[i] = sAT[(tr * 4 + i) * 65 + s];
                float u0 = sU[s * 33 + tcv * 2 + 0];
                float u1 = sU[s * 33 + tcv * 2 + 1];
#pragma unroll
                for (int i = 0; i < 4; i++) { acc[i][0] += av[i] * u0; acc[i][1] += av[i] * u1; }
            }
#pragma unroll
            for (int i = 0; i < 4; i++) {
                size_t oi = rowbase + (size_t)(tr * 4 + i) * DM + dv0 + tcv * 2;
                d_o[oi + 0] = acc[i][0];
                d_o[oi + 1] = acc[i][1];
            }
        }
        __syncthreads();

        // S = dec * S + kd^T @ u
        {
            float acc[4][4];
#pragma unroll
            for (int i = 0; i < 4; i++)
#pragma unroll
                for (int j = 0; j < 4; j++) acc[i][j] = 0.f;
            for (int t = 0; t < 64; t++) {
                float kv[4], uv[4];
#pragma unroll
                for (int i = 0; i < 4; i++) kv[i] = sKT[t * 129 + ur * 4 + i];
#pragma unroll
                for (int j = 0; j < 4; j++) uv[j] = sU[t * 33 + uc * 4 + j];
#pragma unroll
                for (int i = 0; i < 4; i++)
#pragma unroll
                    for (int j = 0; j < 4; j++) acc[i][j] += kv[i] * uv[j];
            }
            const size_t db = (size_t)(bh * NC + c) * 128;
#pragma unroll
            for (int i = 0; i < 4; i++) {
                int d = ur * 4 + i;
                float dc = d_dec[db + d];
#pragma unroll
                for (int j = 0; j < 4; j++) {
                    int v = uc * 4 + j;
                    sS[d * 33 + v] = dc * sS[d * 33 + v] + acc[i][j];
                }
            }
        }
        __syncthreads();
    }
}

// ---------------- rmsnorm * rms_w * gate ----------------
__global__ void rmsgate_kernel(const float* __restrict__ rmsw)
{
    __shared__ float ws[4];
    const int blk = blockIdx.x;           // bt*NH + h
    const int h  = blk % NH;
    const int bt = blk / NH;
    const int d  = threadIdx.x;
    const size_t idx = (size_t)bt * DM + h * DV_ + d;
    float val = d_o[idx];
    float v = val * val;
#pragma unroll
    for (int o = 16; o > 0; o >>= 1) v += __shfl_down_sync(0xffffffffu, v, o);
    int lane = threadIdx.x & 31, wrp = threadIdx.x >> 5;
    if (lane == 0) ws[wrp] = v;
    __syncthreads();
    if (threadIdx.x == 0) ws[0] = ws[0] + ws[1] + ws[2] + ws[3];
    __syncthreads();
    float ms = ws[0] * (1.f / 128.f);
    float scale = rsqrtf(ms + 1e-6f);
    d_og[idx] = val * scale * rmsw[d] * d_gate[idx];
}

// ---------------- host launch ----------------
static float* sym(const void* s) { void* p = nullptr; cudaGetSymbolAddress(&p, s); return (float*)p; }

extern "C" void kernel_launch(void* const* d_in, const int* in_sizes, int n_in,
                              void* d_out, int out_size)
{
    const float* x    = (const float*)d_in[0];
    const float* Wq   = (const float*)d_in[1];
    const float* Wk   = (const float*)d_in[2];
    const float* Wv   = (const float*)d_in[3];
    const float* Wo   = (const float*)d_in[4];
    const float* Wad  = (const float*)d_in[5];
    const float* Wau  = (const float*)d_in[6];
    const float* Wb   = (const float*)d_in[7];
    const float* Wgd  = (const float*)d_in[8];
    const float* Wgu  = (const float*)d_in[9];
    const float* cqw  = (const float*)d_in[10];
    const float* ckw  = (const float*)d_in[11];
    const float* cvw  = (const float*)d_in[12];
    const float* rmsw = (const float*)d_in[13];
    float* out = (float*)d_out;

    float* qpre    = sym(d_qpre);
    float* kpre    = sym(d_kpre);
    float* vpre    = sym(d_vpre);
    float* q_      = sym(d_q);
    float* k_      = sym(d_k);
    float* v_      = sym(d_v);
    float* g_      = sym(d_g);
    float* gate_   = sym(d_gate);
    float* wcat    = sym(d_wcat);
    float* glowcat = sym(d_glowcat);
    float* beta_   = sym(d_beta);
    float* og_     = sym(d_og);

    cudaFuncSetAttribute((const void*)prep_kernel, cudaFuncAttributeMaxDynamicSharedMemorySize, PREP_SMEM);
    cudaFuncSetAttribute((const void*)scan_kernel, cudaFuncAttributeMaxDynamicSharedMemorySize, SCAN_SMEM);
    cudaFuncSetAttribute((const void*)gemm2<128,256>, cudaFuncAttributeMaxDynamicSharedMemorySize, SMEM_G_BIG);
    cudaFuncSetAttribute((const void*)gemm2<128,128>, cudaFuncAttributeMaxDynamicSharedMemorySize, SMEM_G_SML);

    const dim3 gBig(DM / 256, BT / 128);      // (8, 64)
    const dim3 gCat(256 / 128, BT / 128);     // (2, 64)

    // 0: concat low-rank down-proj weights
    cat_kernel<<<(DM * 256) / 256, 256>>>(Wad, Wgd, wcat);
    // 1: fused low-rank down-projections: glowcat = x @ [Wad|Wgd]
    gemm2<128,128><<<gCat, 128, SMEM_G_SML>>>(x, DM, wcat, 256, glowcat, 256, BT, 256, DM);
    // 2: beta
    beta_kernel<<<BT / 8, 256>>>(x, Wb, beta_);

    // 3,4,5: big projections (launch #5 = Wv -> ncu capture target)
    gemm2<128,256><<<gBig, 256, SMEM_G_BIG>>>(x, DM, Wq, DM, qpre, DM, BT, DM, DM);
    gemm2<128,256><<<gBig, 256, SMEM_G_BIG>>>(x, DM, Wk, DM, kpre, DM, BT, DM, DM);
    gemm2<128,256><<<gBig, 256, SMEM_G_BIG>>>(x, DM, Wv, DM, vpre, DM, BT, DM, DM);
    // low-rank up-projections (K=128)
    gemm2<128,256><<<gBig, 256, SMEM_G_BIG>>>(glowcat,       256, Wau, DM, g_,    DM, BT, DM, 128);
    gemm2<128,256><<<gBig, 256, SMEM_G_BIG>>>(glowcat + 128, 256, Wgu, DM, gate_, DM, BT, DM, 128);

    // conv + silu (+ l2norm for q,k)
    conv_silu_kernel<<<BT * NH, 128>>>(qpre, cqw, q_, 1);
    conv_silu_kernel<<<BT * NH, 128>>>(kpre, ckw, k_, 1);
    conv_silu_kernel<<<BT * NH, 128>>>(vpre, cvw, v_, 0);

    // activations
    {
        size_t n = (size_t)BT * DM;
        int nb = (int)((n + 255) / 256);
        gact_kernel<<<nb, 256>>>(g_, n);
        sigmoid_kernel<<<nb, 256>>>(gate_, n);
    }

    // per-chunk prep (parallel over all chunks)
    prep_kernel<<<BB * NH * NC, 256, PREP_SMEM>>>();

    // sequential scan (parallel over b,h,dv-split)
    scan_kernel<<<BB * NH * NVS, 256, SCAN_SMEM>>>();

    // rmsnorm + gate
    rmsgate_kernel<<<BT * NH, 128>>>(rmsw);

    // output projection
    gemm2<128,256><<<gBig, 256, SMEM_G_BIG>>>(og_, DM, Wo, DM, out, DM, BT, DM, DM);
}

// round 7
// speedup vs baseline: 1.1748x; 1.1748x over previous
#include <cuda_runtime.h>
#include <math.h>
#include <stdint.h>

// ---------------- problem constants ----------------
#define BB 2
#define TT 4096
#define BT (BB*TT)          // 8192
#define DM 2048
#define NH 16
#define DK_ 128
#define DV_ 128
#define CH 64               // chunk
#define NC (TT/CH)          // 64 chunks
#define NVS 4               // dv splits in scan
#define WV (DV_/NVS)        // 32

// ---------------- scratch (device globals; no allocs) ----------------
__device__ float d_qpre[(size_t)BT*DM];
__device__ float d_kpre[(size_t)BT*DM];
__device__ float d_vpre[(size_t)BT*DM];
__device__ float d_q[(size_t)BT*DM];
__device__ float d_k[(size_t)BT*DM];
__device__ float d_v[(size_t)BT*DM];
__device__ float d_g[(size_t)BT*DM];
__device__ float d_gate[(size_t)BT*DM];
__device__ float d_glow[(size_t)BT*DK_];
__device__ float d_gatelow[(size_t)BT*DV_];
__device__ float d_beta[(size_t)BT*NH];
__device__ float d_qt[(size_t)BT*DM];
__device__ float d_kt[(size_t)BT*DM];
__device__ float d_kd[(size_t)BT*DM];
__device__ float d_attn[(size_t)BB*NH*NC*CH*CH];
__device__ float d_tinv[(size_t)BB*NH*NC*CH*CH];
__device__ float d_dec[(size_t)BB*NH*NC*DK_];
__device__ float d_o[(size_t)BT*DM];
__device__ float d_og[(size_t)BT*DM];

// ---------------- tf32 helpers ----------------
__device__ __forceinline__ uint32_t f2tf32(float x)
{
    uint32_t y;
    asm("cvt.rna.tf32.f32 %0, %1;" : "=r"(y) : "f"(x));
    return y;
}

__device__ __forceinline__ void mma_tf32(float* c, const uint32_t* a, const uint32_t* b)
{
    asm volatile(
        "mma.sync.aligned.m16n8k8.row.col.f32.tf32.tf32.f32 "
        "{%0,%1,%2,%3}, {%4,%5,%6,%7}, {%8,%9}, {%0,%1,%2,%3};"
        : "+f"(c[0]), "+f"(c[1]), "+f"(c[2]), "+f"(c[3])
        : "r"(a[0]), "r"(a[1]), "r"(a[2]), "r"(a[3]), "r"(b[0]), "r"(b[1]));
}

// ---------------- tf32 tensor-core GEMM (R3 config — known good) ----------------
// BM x 128 block tile, BK=16, 256 threads (8 warps), warp tile (BM/2) x 32.
template<int BM>
__global__ void __launch_bounds__(256) gemm_tf32(const float* __restrict__ A,
                                                 const float* __restrict__ Bm,
                                                 float* __restrict__ C,
                                                 int M, int N, int K)
{
    constexpr int MT = BM / 32;          // m16 tiles per warp
    constexpr int ASD = BM + 8;
    constexpr int BSD = 128 + 8;
    __shared__ uint32_t As[16][ASD];
    __shared__ uint32_t Bs[16][BSD];

    const int bm = blockIdx.y * BM;
    const int bn = blockIdx.x * 128;
    const int tid  = threadIdx.x;
    const int lane = tid & 31;
    const int wid  = tid >> 5;
    const int wm = (wid >> 2) * (BM / 2);
    const int wn = (wid & 3) * 32;

    constexpr int ALD = (BM * 16) / (4 * 256);
    float4 ra[ALD], rb[2];

    float acc[MT][4][4];
#pragma unroll
    for (int mt = 0; mt < MT; mt++)
#pragma unroll
        for (int nt = 0; nt < 4; nt++)
#pragma unroll
            for (int e = 0; e < 4; e++) acc[mt][nt][e] = 0.f;

    auto ldG = [&](int k0) {
#pragma unroll
        for (int i = 0; i < ALD; i++) {
            int lin = tid + i * 256;
            int m = lin >> 2, kq = (lin & 3) * 4;
            ra[i] = *reinterpret_cast<const float4*>(&A[(size_t)(bm + m) * K + k0 + kq]);
        }
#pragma unroll
        for (int i = 0; i < 2; i++) {
            int lin = tid + i * 256;
            int kk = lin >> 5, nq = (lin & 31) * 4;
            rb[i] = *reinterpret_cast<const float4*>(&Bm[(size_t)(k0 + kk) * N + bn + nq]);
        }
    };
    auto stS = [&]() {
#pragma unroll
        for (int i = 0; i < ALD; i++) {
            int lin = tid + i * 256;
            int m = lin >> 2, kq = (lin & 3) * 4;
            As[kq + 0][m] = f2tf32(ra[i].x);
            As[kq + 1][m] = f2tf32(ra[i].y);
            As[kq + 2][m] = f2tf32(ra[i].z);
            As[kq + 3][m] = f2tf32(ra[i].w);
        }
#pragma unroll
        for (int i = 0; i < 2; i++) {
            int lin = tid + i * 256;
            int kk = lin >> 5, nq = (lin & 31) * 4;
            Bs[kk][nq + 0] = f2tf32(rb[i].x);
            Bs[kk][nq + 1] = f2tf32(rb[i].y);
            Bs[kk][nq + 2] = f2tf32(rb[i].z);
            Bs[kk][nq + 3] = f2tf32(rb[i].w);
        }
    };

    ldG(0);
    stS();
    __syncthreads();

    for (int k0 = 0; k0 < K; k0 += 16) {
        const bool nxt = (k0 + 16) < K;
        if (nxt) ldG(k0 + 16);
#pragma unroll
        for (int ks = 0; ks < 16; ks += 8) {
            uint32_t af[MT][4];
#pragma unroll
            for (int mt = 0; mt < MT; mt++) {
                int r  = wm + mt * 16 + (lane >> 2);
                int kc = ks + (lane & 3);
                af[mt][0] = As[kc][r];
                af[mt][1] = As[kc][r + 8];
                af[mt][2] = As[kc + 4][r];
                af[mt][3] = As[kc + 4][r + 8];
            }
            uint32_t bf[4][2];
#pragma unroll
            for (int nt = 0; nt < 4; nt++) {
                int cN = wn + nt * 8 + (lane >> 2);
                int kc = ks + (lane & 3);
                bf[nt][0] = Bs[kc][cN];
                bf[nt][1] = Bs[kc + 4][cN];
            }
#pragma unroll
            for (int mt = 0; mt < MT; mt++)
#pragma unroll
                for (int nt = 0; nt < 4; nt++)
                    mma_tf32(acc[mt][nt], af[mt], bf[nt]);
        }
        __syncthreads();
        if (nxt) { stS(); __syncthreads(); }
    }

#pragma unroll
    for (int mt = 0; mt < MT; mt++) {
        int r0 = bm + wm + mt * 16 + (lane >> 2);
#pragma unroll
        for (int nt = 0; nt < 4; nt++) {
            int c0 = bn + wn + nt * 8 + (lane & 3) * 2;
            *reinterpret_cast<float2*>(&C[(size_t)r0 * N + c0]) =
                make_float2(acc[mt][nt][0], acc[mt][nt][1]);
            *reinterpret_cast<float2*>(&C[(size_t)(r0 + 8) * N + c0]) =
                make_float2(acc[mt][nt][2], acc[mt][nt][3]);
        }
    }
}

// ---------------- fused beta = sigmoid(clip(x @ Wb)) ----------------
__global__ void beta_kernel(const float* __restrict__ x, const float* __restrict__ Wb,
                            float* __restrict__ beta)
{
    __shared__ float wbs[256][17];
    const int tid  = threadIdx.x;
    const int lane = tid & 31;
    const int wid  = tid >> 5;
    const int row  = blockIdx.x * 8 + wid;

    float acc[16];
#pragma unroll
    for (int c = 0; c < 16; c++) acc[c] = 0.f;

    for (int k0 = 0; k0 < DM; k0 += 256) {
        __syncthreads();
        {
            const float* src = &Wb[(size_t)(k0 + tid) * 16];
#pragma unroll
            for (int c = 0; c < 16; c++) wbs[tid][c] = src[c];
        }
        __syncthreads();
#pragma unroll
        for (int k8 = 0; k8 < 8; k8++) {
            float xv = x[(size_t)row * DM + k0 + k8 * 32 + lane];
#pragma unroll
            for (int c = 0; c < 16; c++) acc[c] += xv * wbs[k8 * 32 + lane][c];
        }
    }
#pragma unroll
    for (int c = 0; c < 16; c++) {
#pragma unroll
        for (int off = 16; off; off >>= 1)
            acc[c] += __shfl_xor_sync(0xffffffffu, acc[c], off);
    }
    if (lane == 0) {
#pragma unroll
        for (int c = 0; c < 16; c++) {
            float v = fminf(fmaxf(acc[c], -10.f), 10.f);
            beta[(size_t)row * 16 + c] = 1.f / (1.f + expf(-v));
        }
    }
}

// ---------------- causal depthwise conv (K=4) + silu (+ per-head l2norm) ----------------
__global__ void conv_silu_kernel(const float* __restrict__ pre, const float* __restrict__ w,
                                 float* __restrict__ out, int do_norm)
{
    __shared__ float ws[4];
    const int blk = blockIdx.x;               // (b*T + t)*NH + h
    const int h  = blk % NH;
    const int bt = blk / NH;
    const int t  = bt % TT;
    const int d  = threadIdx.x;               // 0..127
    const int c  = h * DK_ + d;

    float acc = 0.f;
#pragma unroll
    for (int j = 0; j < 4; j++) {
        int tt = t - 3 + j;
        if (tt >= 0) acc += w[c * 4 + j] * pre[(size_t)(bt - 3 + j) * DM + c];
    }
    float s = acc / (1.f + expf(-acc));       // silu
    if (do_norm) {
        float v = s * s;
#pragma unroll
        for (int o = 16; o > 0; o >>= 1) v += __shfl_down_sync(0xffffffffu, v, o);
        int lane = threadIdx.x & 31, wrp = threadIdx.x >> 5;
        if (lane == 0) ws[wrp] = v;
        __syncthreads();
        if (threadIdx.x == 0) ws[0] = ws[0] + ws[1] + ws[2] + ws[3];
        __syncthreads();
        float n = sqrtf(ws[0]);
        s = s / fmaxf(n, 1e-6f);
    }
    out[(size_t)bt * DM + c] = s;
}

// ---------------- per-chunk prep (softplus activation fused into cumsum) ----------------
#define PREP_SMEM ((4*64*129 + 2*64*65 + 128 + 64) * 4)
__global__ void prep_kernel()
{
    extern __shared__ float sm[];
    float* s_cum = sm;                    // 64*129
    float* s_kt  = s_cum + 64 * 129;
    float* s_kb  = s_kt  + 64 * 129;
    float* s_qt  = s_kb  + 64 * 129;
    float* s_M   = s_qt  + 64 * 129;      // 64*65
    float* s_X   = s_M   + 64 * 65;       // 64*65
    float* s_bl  = s_X   + 64 * 65;       // 128
    float* s_be  = s_bl  + 128;           // 64

    const int blk = blockIdx.x;           // bh*NC + c
    const int c   = blk % NC;
    const int bh  = blk / NC;
    const int h   = bh % NH;
    const int b   = bh / NH;
    const int t0  = c * CH;
    const int tid = threadIdx.x;
    const size_t rowbase = (size_t)(b * TT + t0) * DM + h * DK_;

    if (tid < 128) {
        float run = 0.f;
        for (int t = 0; t < CH; t++) {
            float raw = d_g[rowbase + (size_t)t * DM + tid];
            raw = fminf(fmaxf(raw, -10.f), 10.f);
            run += -log1pf(expf(raw));    // g = -softplus(clip(raw))
            s_cum[t * 129 + tid] = run;
        }
        s_bl[tid] = run;
    }
    if (tid < 64) s_be[tid] = d_beta[(size_t)(b * TT + t0 + tid) * NH + h];
    __syncthreads();

    for (int idx = tid; idx < CH * 128; idx += 256) {
        int t = idx >> 7, d = idx & 127;
        float cum = s_cum[t * 129 + d];
        size_t gi = rowbase + (size_t)t * DM + d;
        float kv = d_k[gi];
        float qv = d_q[gi];
        float e  = expf(cum);
        float kt = kv * e;
        float qt = qv * e;
        float kb = kv * expf(-cum);
        float kd = kv * expf(s_bl[d] - cum);
        s_kt[t * 129 + d] = kt;
        s_qt[t * 129 + d] = qt;
        s_kb[t * 129 + d] = kb;
        d_kt[gi] = kt;
        d_qt[gi] = qt;
        d_kd[gi] = kd;
    }
    if (tid < 128) d_dec[(size_t)blk * 128 + tid] = expf(s_bl[tid]);
    __syncthreads();

    const size_t ab = (size_t)blk * (CH * CH);
    {
        const int tI = (tid >> 4) * 4;
        const int sI = (tid & 15) * 4;
        float a[4][4], at[4][4];
#pragma unroll
        for (int i = 0; i < 4; i++)
#pragma unroll
            for (int j = 0; j < 4; j++) { a[i][j] = 0.f; at[i][j] = 0.f; }
        for (int d = 0; d < 128; d++) {
            float kbv[4], ktv[4], qtv[4];
#pragma unroll
            for (int j = 0; j < 4; j++) kbv[j] = s_kb[(sI + j) * 129 + d];
#pragma unroll
            for (int i = 0; i < 4; i++) { ktv[i] = s_kt[(tI + i) * 129 + d]; qtv[i] = s_qt[(tI + i) * 129 + d]; }
#pragma unroll
            for (int i = 0; i < 4; i++)
#pragma unroll
                for (int j = 0; j < 4; j++) { a[i][j] += ktv[i] * kbv[j]; at[i][j] += qtv[i] * kbv[j]; }
        }
#pragma unroll
        for (int i = 0; i < 4; i++)
#pragma unroll
            for (int j = 0; j < 4; j++) {
                int t = tI + i, s = sI + j;
                s_M[t * 65 + s] = (s < t) ? s_be[t] * a[i][j] : 0.f;
                d_attn[ab + t * 64 + s] = (s <= t) ? at[i][j] : 0.f;
            }
    }
    __syncthreads();

    if (tid < 64) {
        const int j = tid;
        for (int i = 0; i < 64; i++) {
            float x = (i == j) ? 1.f : 0.f;
            for (int l = j; l < i; l++) x -= s_M[i * 65 + l] * s_X[l * 65 + j];
            s_X[i * 65 + j] = x;
        }
        float bj = s_be[j];
        for (int i = 0; i < 64; i++)
            d_tinv[ab + i * 64 + j] = s_X[i * 65 + j] * bj;
    }
}

// ---------------- sequential chunk scan — tensor-core version ----------------
// Strides chosen so all fragment access patterns are bank-conflict-free:
//   time-major tiles (kt/qt/kd): stride 136  (136 mod 32 = 8)
//   attn/tinv:                   stride 72   (72  mod 32 = 8)
//   S / rhs / u (fp32):          stride 40   (40  mod 32 = 8)
// Scan runs at 1 block/SM (smem-bound), so register caching is free:
// the S fragments converted in phase b are reused verbatim in phase d.
#define TSTR 136
#define ASTR 72
#define VSTR 40
#define SCAN_SMEM ((128*VSTR + 2*64*TSTR + 2*64*ASTR + 2*64*VSTR + 128) * 4)
__global__ void __launch_bounds__(256) scan_kernel()
{
    extern __shared__ float sm[];
    float* sS   = sm;                      // 128 x VSTR (fp32, persistent)
    float* sKT  = sS  + 128 * VSTR;        // 64 x TSTR (tf32 bits: kt, later kd)
    float* sQT  = sKT + 64 * TSTR;         // 64 x TSTR (tf32 bits)
    float* sAT  = sQT + 64 * TSTR;         // 64 x ASTR (tf32 bits)
    float* sTI  = sAT + 64 * ASTR;         // 64 x ASTR (tf32 bits)
    float* sRH  = sTI + 64 * ASTR;         // 64 x VSTR (fp32: v then rhs)
    float* sU   = sRH + 64 * VSTR;         // 64 x VSTR (fp32)
    float* sDec = sU  + 64 * VSTR;         // 128

    const int blk = blockIdx.x;           // bh*NVS + vb
    const int vb  = blk % NVS;
    const int bh  = blk / NVS;
    const int h   = bh % NH;
    const int b   = bh / NH;
    const int dv0 = vb * WV;
    const int tid = threadIdx.x;
    const int lane = tid & 31;
    const int wp   = tid >> 5;            // warp 0..7
    const int gr   = lane >> 2;           // 0..7
    const int gc   = lane & 3;            // 0..3

    // phases b/c/d tiling: 64x32 out = 4 m-tiles x 4 n-tiles; warp: 1 m-tile, 2 n-tiles
    const int mt  = wp >> 1;              // 0..3
    const int np  = wp & 1;               // 0..1
    const int r0  = mt * 16;
    const int cb0 = np * 16;

    // cached S B-fragments (filled in phase b, reused in phase d; same values)
    uint32_t sfrag[16][2][2];

    for (int i = tid; i < 128 * VSTR; i += 256) sS[i] = 0.f;
    __syncthreads();

    for (int c = 0; c < NC; c++) {
        const int t0 = c * CH;
        const size_t rowbase = (size_t)(b * TT + t0) * DM + h * DK_;
        const size_t ab = (size_t)(bh * NC + c) * (CH * CH);

        // ---- chunk loads (kt/qt/attn/tinv pre-converted to tf32 bits) ----
        for (int i = tid; i < CH * 128; i += 256) {
            int t = i >> 7, d = i & 127;
            size_t gi = rowbase + (size_t)t * DM + d;
            sKT[t * TSTR + d] = __uint_as_float(f2tf32(d_kt[gi]));
            sQT[t * TSTR + d] = __uint_as_float(f2tf32(d_qt[gi]));
        }
        for (int i = tid; i < CH * CH; i += 256) {
            int t = i >> 6, s = i & 63;
            sAT[t * ASTR + s] = __uint_as_float(f2tf32(d_attn[ab + i]));
            sTI[t * ASTR + s] = __uint_as_float(f2tf32(d_tinv[ab + i]));
        }
        for (int i = tid; i < CH * WV; i += 256) {
            int t = i >> 5, v = i & 31;
            sRH[t * VSTR + v] = d_v[rowbase + (size_t)t * DM + dv0 + v];
        }
        if (tid < 128) sDec[tid] = d_dec[(size_t)(bh * NC + c) * 128 + tid];
        __syncthreads();

        // ---- phase b: rhs = v - kt @ S   (64x32, contract 128) ----
        {
            float acc[2][4] = {{0.f,0.f,0.f,0.f},{0.f,0.f,0.f,0.f}};
#pragma unroll
            for (int ks = 0; ks < 128; ks += 8) {
                uint32_t a[4];
                const float* Ab = sKT + r0 * TSTR + ks + gc;
                a[0] = __float_as_uint(Ab[gr * TSTR]);
                a[1] = __float_as_uint(Ab[(gr + 8) * TSTR]);
                a[2] = __float_as_uint(Ab[gr * TSTR + 4]);
                a[3] = __float_as_uint(Ab[(gr + 8) * TSTR + 4]);
#pragma unroll
                for (int nt = 0; nt < 2; nt++) {
                    int cc = cb0 + nt * 8 + gr;
                    uint32_t bfr[2];
                    bfr[0] = f2tf32(sS[(ks + gc) * VSTR + cc]);
                    bfr[1] = f2tf32(sS[(ks + gc + 4) * VSTR + cc]);
                    sfrag[ks >> 3][nt][0] = bfr[0];
                    sfrag[ks >> 3][nt][1] = bfr[1];
                    mma_tf32(acc[nt], a, bfr);
                }
            }
#pragma unroll
            for (int nt = 0; nt < 2; nt++) {
                int cc = cb0 + nt * 8 + gc * 2;
                sRH[(r0 + gr) * VSTR + cc]         -= acc[nt][0];
                sRH[(r0 + gr) * VSTR + cc + 1]     -= acc[nt][1];
                sRH[(r0 + gr + 8) * VSTR + cc]     -= acc[nt][2];
                sRH[(r0 + gr + 8) * VSTR + cc + 1] -= acc[nt][3];
            }
        }
        __syncthreads();

        // reload kd into sKT (phase c doesn't touch sKT)
        for (int i = tid; i < CH * 128; i += 256) {
            int t = i >> 7, d = i & 127;
            sKT[t * TSTR + d] = __uint_as_float(f2tf32(d_kd[rowbase + (size_t)t * DM + d]));
        }

        // ---- phase c: u = Tinv' @ rhs  (64x32, contract 64) ----
        {
            float acc[2][4] = {{0.f,0.f,0.f,0.f},{0.f,0.f,0.f,0.f}};
#pragma unroll
            for (int ks = 0; ks < 64; ks += 8) {
                uint32_t a[4];
                const float* Ab = sTI + r0 * ASTR + ks + gc;
                a[0] = __float_as_uint(Ab[gr * ASTR]);
                a[1] = __float_as_uint(Ab[(gr + 8) * ASTR]);
                a[2] = __float_as_uint(Ab[gr * ASTR + 4]);
                a[3] = __float_as_uint(Ab[(gr + 8) * ASTR + 4]);
#pragma unroll
                for (int nt = 0; nt < 2; nt++) {
                    int cc = cb0 + nt * 8 + gr;
                    uint32_t bfr[2];
                    bfr[0] = f2tf32(sRH[(ks + gc) * VSTR + cc]);
                    bfr[1] = f2tf32(sRH[(ks + gc + 4) * VSTR + cc]);
                    mma_tf32(acc[nt], a, bfr);
                }
            }
#pragma unroll
            for (int nt = 0; nt < 2; nt++) {
                int cc = cb0 + nt * 8 + gc * 2;
                sU[(r0 + gr) * VSTR + cc]         = acc[nt][0];
                sU[(r0 + gr) * VSTR + cc + 1]     = acc[nt][1];
                sU[(r0 + gr + 8) * VSTR + cc]     = acc[nt][2];
                sU[(r0 + gr + 8) * VSTR + cc + 1] = acc[nt][3];
            }
        }
        __syncthreads();

        // ---- phase d: o = qt @ S + attn @ u  -> global ----
        {
            float acc[2][4] = {{0.f,0.f,0.f,0.f},{0.f,0.f,0.f,0.f}};
#pragma unroll
            for (int ks = 0; ks < 128; ks += 8) {
                uint32_t a[4];
                const float* Ab = sQT + r0 * TSTR + ks + gc;
                a[0] = __float_as_uint(Ab[gr * TSTR]);
                a[1] = __float_as_uint(Ab[(gr + 8) * TSTR]);
                a[2] = __float_as_uint(Ab[gr * TSTR + 4]);
                a[3] = __float_as_uint(Ab[(gr + 8) * TSTR + 4]);
#pragma unroll
                for (int nt = 0; nt < 2; nt++) {
                    // S unchanged since phase b -> reuse cached fragments
                    mma_tf32(acc[nt], a, sfrag[ks >> 3][nt]);
                }
            }
#pragma unroll
            for (int ks = 0; ks < 64; ks += 8) {
                uint32_t a[4];
                const float* Ab = sAT + r0 * ASTR + ks + gc;
                a[0] = __float_as_uint(Ab[gr * ASTR]);
                a[1] = __float_as_uint(Ab[(gr + 8) * ASTR]);
                a[2] = __float_as_uint(Ab[gr * ASTR + 4]);
                a[3] = __float_as_uint(Ab[(gr + 8) * ASTR + 4]);
#pragma unroll
                for (int nt = 0; nt < 2; nt++) {
                    int cc = cb0 + nt * 8 + gr;
                    uint32_t bfr[2];
                    bfr[0] = f2tf32(sU[(ks + gc) * VSTR + cc]);
                    bfr[1] = f2tf32(sU[(ks + gc + 4) * VSTR + cc]);
                    mma_tf32(acc[nt], a, bfr);
                }
            }
#pragma unroll
            for (int nt = 0; nt < 2; nt++) {
                int cc = cb0 + nt * 8 + gc * 2;
                *reinterpret_cast<float2*>(&d_o[rowbase + (size_t)(r0 + gr) * DM + dv0 + cc]) =
                    make_float2(acc[nt][0], acc[nt][1]);
                *reinterpret_cast<float2*>(&d_o[rowbase + (size_t)(r0 + gr + 8) * DM + dv0 + cc]) =
                    make_float2(acc[nt][2], acc[nt][3]);
            }
        }
        __syncthreads();

        // ---- phase e: S = dec * S + kd^T @ u  (128x32, contract 64) ----
        {
            const int m0 = wp * 16;       // warp owns 16 d-rows, all 4 n-tiles
            float acc[4][4];
#pragma unroll
            for (int nt = 0; nt < 4; nt++)
#pragma unroll
                for (int e = 0; e < 4; e++) acc[nt][e] = 0.f;
#pragma unroll
            for (int ks = 0; ks < 64; ks += 8) {
                uint32_t a[4];
                a[0] = __float_as_uint(sKT[(ks + gc) * TSTR + m0 + gr]);
                a[1] = __float_as_uint(sKT[(ks + gc) * TSTR + m0 + gr + 8]);
                a[2] = __float_as_uint(sKT[(ks + gc + 4) * TSTR + m0 + gr]);
                a[3] = __float_as_uint(sKT[(ks + gc + 4) * TSTR + m0 + gr + 8]);
#pragma unroll
                for (int nt = 0; nt < 4; nt++) {
                    int cc = nt * 8 + gr;
                    uint32_t bfr[2];
                    bfr[0] = f2tf32(sU[(ks + gc) * VSTR + cc]);
                    bfr[1] = f2tf32(sU[(ks + gc + 4) * VSTR + cc]);
                    mma_tf32(acc[nt], a, bfr);
                }
            }
            const float dlo = sDec[m0 + gr];
            const float dhi = sDec[m0 + gr + 8];
#pragma unroll
            for (int nt = 0; nt < 4; nt++) {
                int cc = nt * 8 + gc * 2;
                int i1 = (m0 + gr) * VSTR + cc;
                int i2 = (m0 + gr + 8) * VSTR + cc;
                sS[i1]     = dlo * sS[i1]     + acc[nt][0];
                sS[i1 + 1] = dlo * sS[i1 + 1] + acc[nt][1];
                sS[i2]     = dhi * sS[i2]     + acc[nt][2];
                sS[i2 + 1] = dhi * sS[i2 + 1] + acc[nt][3];
            }
        }
        __syncthreads();
    }
}

// ---------------- rmsnorm * rms_w * sigmoid(gate) ----------------
__global__ void rmsgate_kernel(const float* __restrict__ rmsw)
{
    __shared__ float ws[4];
    const int blk = blockIdx.x;           // bt*NH + h
    const int h  = blk % NH;
    const int bt = blk / NH;
    const int d  = threadIdx.x;
    const size_t idx = (size_t)bt * DM + h * DV_ + d;
    float val = d_o[idx];
    float v = val * val;
#pragma unroll
    for (int o = 16; o > 0; o >>= 1) v += __shfl_down_sync(0xffffffffu, v, o);
    int lane = threadIdx.x & 31, wrp = threadIdx.x >> 5;
    if (lane == 0) ws[wrp] = v;
    __syncthreads();
    if (threadIdx.x == 0) ws[0] = ws[0] + ws[1] + ws[2] + ws[3];
    __syncthreads();
    float ms = ws[0] * (1.f / 128.f);
    float scale = rsqrtf(ms + 1e-6f);
    float gate = 1.f / (1.f + expf(-d_gate[idx]));     // sigmoid fused here
    d_og[idx] = val * scale * rmsw[d] * gate;
}

// ---------------- host launch ----------------
static float* sym(const void* s) { void* p = nullptr; cudaGetSymbolAddress(&p, s); return (float*)p; }

extern "C" void kernel_launch(void* const* d_in, const int* in_sizes, int n_in,
                              void* d_out, int out_size)
{
    const float* x    = (const float*)d_in[0];
    const float* Wq   = (const float*)d_in[1];
    const float* Wk   = (const float*)d_in[2];
    const float* Wv   = (const float*)d_in[3];
    const float* Wo   = (const float*)d_in[4];
    const float* Wad  = (const float*)d_in[5];
    const float* Wau  = (const float*)d_in[6];
    const float* Wb   = (const float*)d_in[7];
    const float* Wgd  = (const float*)d_in[8];
    const float* Wgu  = (const float*)d_in[9];
    const float* cqw  = (const float*)d_in[10];
    const float* ckw  = (const float*)d_in[11];
    const float* cvw  = (const float*)d_in[12];
    const float* rmsw = (const float*)d_in[13];
    float* out = (float*)d_out;

    float* qpre    = sym(d_qpre);
    float* kpre    = sym(d_kpre);
    float* vpre    = sym(d_vpre);
    float* q_      = sym(d_q);
    float* k_      = sym(d_k);
    float* v_      = sym(d_v);
    float* g_      = sym(d_g);
    float* gate_   = sym(d_gate);
    float* glow    = sym(d_glow);
    float* gatelow = sym(d_gatelow);
    float* beta_   = sym(d_beta);
    float* og_     = sym(d_og);

    cudaFuncSetAttribute((const void*)prep_kernel, cudaFuncAttributeMaxDynamicSharedMemorySize, PREP_SMEM);
    cudaFuncSetAttribute((const void*)scan_kernel, cudaFuncAttributeMaxDynamicSharedMemorySize, SCAN_SMEM);

    const dim3 gBig(DM / 128, BT / 128);      // (16, 64)
    const dim3 gLowA(1, BT / 64);             // (1, 128) for BM=64, N=128
    const dim3 blk256(256);

    // low-rank down-projections + beta first (ncu capture slot 5 = big GEMM)
    gemm_tf32<64><<<gLowA, blk256>>>(x, Wad, glow, BT, DK_, DM);       // 0
    gemm_tf32<64><<<gLowA, blk256>>>(x, Wgd, gatelow, BT, DV_, DM);    // 1
    beta_kernel<<<BT / 8, blk256>>>(x, Wb, beta_);                     // 2

    // big projections
    gemm_tf32<128><<<gBig, blk256>>>(x, Wq, qpre, BT, DM, DM);         // 3
    gemm_tf32<128><<<gBig, blk256>>>(x, Wk, kpre, BT, DM, DM);         // 4
    gemm_tf32<128><<<gBig, blk256>>>(x, Wv, vpre, BT, DM, DM);         // 5 <- ncu capture
    gemm_tf32<128><<<gBig, blk256>>>(glow, Wau, g_, BT, DM, DK_);      // 6 (raw; softplus fused into prep)
    gemm_tf32<128><<<gBig, blk256>>>(gatelow, Wgu, gate_, BT, DM, DV_);// 7 (raw; sigmoid fused into rmsgate)

    // conv + silu (+ l2norm for q,k)
    conv_silu_kernel<<<BT * NH, 128>>>(qpre, cqw, q_, 1);
    conv_silu_kernel<<<BT * NH, 128>>>(kpre, ckw, k_, 1);
    conv_silu_kernel<<<BT * NH, 128>>>(vpre, cvw, v_, 0);

    // per-chunk prep (parallel over all chunks)
    prep_kernel<<<BB * NH * NC, 256, PREP_SMEM>>>();

    // sequential scan (parallel over b,h,dv-split) — tensor-core phases
    scan_kernel<<<BB * NH * NVS, 256, SCAN_SMEM>>>();

    // rmsnorm + sigmoid(gate)
    rmsgate_kernel<<<BT * NH, 128>>>(rmsw);

    // output projection
    gemm_tf32<128><<<gBig, blk256>>>(og_, Wo, out, BT, DM, DM);
}